// round 1
// baseline (speedup 1.0000x reference)
#include <cuda_runtime.h>
#include <math.h>

// XConv fused kernel for GB300 (sm_103a)
// Shapes: N=16,P=1024,K=16,DIMS=3,C_IN=64,C_MID=64,C_CAT=128,KK=256,DM=4,C_OUT=128
// One CTA handles G=8 points with 256 threads; all stages fused; fp32 throughout.

namespace {

constexpr int KNB   = 16;    // K neighbors
constexpr int G     = 8;     // points per CTA
constexpr int T     = 256;   // threads per CTA
constexpr int CCAT  = 128;

// shared memory layout (float offsets)
constexpr int OFF_W1  = 0;       // 192  (w1 3x64)
constexpr int OFF_B1  = 192;     // 64
constexpr int OFF_B2  = 256;     // 64
constexpr int OFF_PLT = 320;     // 384  (plT[g][d][k])
constexpr int OFF_FC  = 704;     // 16384 (fts_cat[g][k][128])
constexpr int OFF_WS  = 17088;   // 12544 (union: w2 4096 / wc1 pitched 256*49 / wdwT 64*132)
constexpr int OFF_R   = 29632;   // 8448  (union: h1 128*66 / X0T 2048 + X1T 2048 / dw 4096)
constexpr int SMEM_FLOATS = 38080;  // 152320 bytes

__device__ __forceinline__ float elu1(float x) { return x > 0.f ? x : expm1f(x); }

__global__ void __launch_bounds__(T, 1)
xconv_kernel(const float* __restrict__ rep_pt, const float* __restrict__ pts,
             const float* __restrict__ fts,
             const float* __restrict__ w1,  const float* __restrict__ b1,
             const float* __restrict__ w2,  const float* __restrict__ b2,
             const float* __restrict__ wc1, const float* __restrict__ bc1,
             const float* __restrict__ wx1, const float* __restrict__ bx1,
             const float* __restrict__ wx2, const float* __restrict__ bx2,
             const float* __restrict__ wdw, const float* __restrict__ bdw,
             const float* __restrict__ wpw, const float* __restrict__ bpw,
             const float* __restrict__ bng, const float* __restrict__ bnb,
             const float* __restrict__ bnm, const float* __restrict__ bnv,
             float* __restrict__ out)
{
    extern __shared__ float sm[];
    float* w1s = sm + OFF_W1;
    float* b1s = sm + OFF_B1;
    float* b2s = sm + OFF_B2;
    float* plT = sm + OFF_PLT;   // [g][d][k] : g*48 + d*16 + k
    float* fc  = sm + OFF_FC;    // [g*16+k][128]
    float* ws  = sm + OFF_WS;    // scratch weights
    float* R   = sm + OFF_R;     // scratch activations

    const int t = threadIdx.x;
    const int pbase = blockIdx.x * G;

    // ---- Stage A0: loads ----
    for (int i = t; i < 192; i += T) w1s[i] = w1[i];
    if (t < 64) { b1s[t] = b1[t]; b2s[t] = b2[t]; }
    for (int i = t; i < 4096; i += T) ws[i] = w2[i];   // w2 into scratch

    // pts_local, transposed: plT[g][d][k]
    for (int i = t; i < G * 48; i += T) {
        int g = i / 48, r = i - g * 48, d = r >> 4, k = r & 15;
        int pp = pbase + g;
        plT[i] = pts[(pp * KNB + k) * 3 + d] - rep_pt[pp * 3 + d];
    }
    // copy fts into fts_cat columns 64..127 (coalesced reads)
    for (int i = t; i < G * KNB * 64; i += T) {
        int g = i >> 10, rem = i & 1023, k = rem >> 6, c = rem & 63;
        fc[(g * KNB + k) * CCAT + 64 + c] = fts[(size_t)(pbase + g) * 1024 + rem];
    }
    __syncthreads();

    // ---- Stage A1: h1 = elu(pl @ w1 + b1)  (128 rows x 64 cols, pitch 66) ----
    float* h1 = R;
    {
        int row = t >> 1, g = row >> 4, k = row & 15, cb = (t & 1) * 32;
        float p0 = plT[g * 48 + k];
        float p1 = plT[g * 48 + 16 + k];
        float p2 = plT[g * 48 + 32 + k];
        #pragma unroll
        for (int c = 0; c < 32; c++) {
            float a = b1s[cb + c] + p0 * w1s[cb + c] + p1 * w1s[64 + cb + c]
                      + p2 * w1s[128 + cb + c];
            h1[row * 66 + cb + c] = elu1(a);
        }
    }
    __syncthreads();

    // ---- Stage A2: h2 = elu(h1 @ w2 + b2) -> fc[:, 0:64] ----
    {
        int tc = t & 7, tr = t >> 3;           // 8 col-groups x 32 row-groups
        float acc[4][8];
        #pragma unroll
        for (int i = 0; i < 4; i++)
            #pragma unroll
            for (int c = 0; c < 8; c++) acc[i][c] = b2s[tc * 8 + c];
        #pragma unroll 4
        for (int j = 0; j < 64; j++) {
            float4 wA = *(const float4*)&ws[j * 64 + tc * 8];
            float4 wB = *(const float4*)&ws[j * 64 + tc * 8 + 4];
            #pragma unroll
            for (int i = 0; i < 4; i++) {
                float hv = h1[(tr * 4 + i) * 66 + j];
                acc[i][0] += hv * wA.x; acc[i][1] += hv * wA.y;
                acc[i][2] += hv * wA.z; acc[i][3] += hv * wA.w;
                acc[i][4] += hv * wB.x; acc[i][5] += hv * wB.y;
                acc[i][6] += hv * wB.z; acc[i][7] += hv * wB.w;
            }
        }
        #pragma unroll
        for (int i = 0; i < 4; i++) {
            int row = tr * 4 + i;
            float4 o0 = {elu1(acc[i][0]), elu1(acc[i][1]), elu1(acc[i][2]), elu1(acc[i][3])};
            float4 o1 = {elu1(acc[i][4]), elu1(acc[i][5]), elu1(acc[i][6]), elu1(acc[i][7])};
            *(float4*)&fc[row * CCAT + tc * 8]     = o0;
            *(float4*)&fc[row * CCAT + tc * 8 + 4] = o1;
        }
    }
    __syncthreads();

    // ---- Stage B prep: wc1 into scratch, padded pitch 49 (bank-conflict-free) ----
    for (int i = t; i < 256 * 48; i += T) {
        int o = i / 48, m = i - o * 48;
        ws[o * 49 + m] = wc1[i];
    }
    __syncthreads();

    // ---- Stage B: X0 = elu(pl_flat @ wc1^T + bc1), stored transposed X0T[o][g] ----
    float* X0T = R;            // 256*8
    float* X1T = R + 2048;     // 256*8
    {
        int g = t >> 5, lane = t & 31;
        float acc[8];
        #pragma unroll
        for (int q = 0; q < 8; q++) acc[q] = bc1[lane + 32 * q];
        const float* pg = plT + g * 48;
        for (int m = 0; m < 48; m++) {
            float pv = pg[m];
            #pragma unroll
            for (int q = 0; q < 8; q++) acc[q] += pv * ws[(lane + 32 * q) * 49 + m];
        }
        #pragma unroll
        for (int q = 0; q < 8; q++) X0T[(lane + 32 * q) * 8 + g] = elu1(acc[q]);
    }
    __syncthreads();

    // ---- Stage C1: X1 = elu(X0 @ wx1 + bx1) ----
    {
        int c = t;
        float acc[8];
        float bb = bx1[c];
        #pragma unroll
        for (int g = 0; g < 8; g++) acc[g] = bb;
        const float* wcol = wx1 + c;
        #pragma unroll 8
        for (int j = 0; j < 256; j++) {
            float w = wcol[j * 256];
            float4 xa = *(const float4*)&X0T[j * 8];
            float4 xb = *(const float4*)&X0T[j * 8 + 4];
            acc[0] += xa.x * w; acc[1] += xa.y * w; acc[2] += xa.z * w; acc[3] += xa.w * w;
            acc[4] += xb.x * w; acc[5] += xb.y * w; acc[6] += xb.z * w; acc[7] += xb.w * w;
        }
        float4 o0 = {elu1(acc[0]), elu1(acc[1]), elu1(acc[2]), elu1(acc[3])};
        float4 o1 = {elu1(acc[4]), elu1(acc[5]), elu1(acc[6]), elu1(acc[7])};
        *(float4*)&X1T[c * 8]     = o0;
        *(float4*)&X1T[c * 8 + 4] = o1;
    }
    __syncthreads();

    // ---- Stage C2: Xf = X1 @ wx2 + bx2 (no activation) -> X0T ----
    {
        int c = t;
        float acc[8];
        float bb = bx2[c];
        #pragma unroll
        for (int g = 0; g < 8; g++) acc[g] = bb;
        const float* wcol = wx2 + c;
        #pragma unroll 8
        for (int j = 0; j < 256; j++) {
            float w = wcol[j * 256];
            float4 xa = *(const float4*)&X1T[j * 8];
            float4 xb = *(const float4*)&X1T[j * 8 + 4];
            acc[0] += xa.x * w; acc[1] += xa.y * w; acc[2] += xa.z * w; acc[3] += xa.w * w;
            acc[4] += xb.x * w; acc[5] += xb.y * w; acc[6] += xb.z * w; acc[7] += xb.w * w;
        }
        float4 o0 = {acc[0], acc[1], acc[2], acc[3]};
        float4 o1 = {acc[4], acc[5], acc[6], acc[7]};
        *(float4*)&X0T[c * 8]     = o0;
        *(float4*)&X0T[c * 8 + 4] = o1;
    }
    __syncthreads();

    // ---- Stage D prep: wdwT[d*16+k][c] into scratch, pitch 132 ----
    // (wc1 is dead; reads of wdw coalesced; 4-way-conflict stores, negligible)
    for (int i = t; i < 8192; i += T) {
        int c = i >> 6, r = i & 63;          // r = d*16 + k
        ws[r * 132 + c] = wdw[i];
    }
    __syncthreads();

    // ---- Stage D: fts_X = X @ fts_cat, then depthwise -> dw[g][512] ----
    float* dws = R + 2048;   // overwrites dead X1T; Xf in R[0..2047] stays live
    {
        int g = t >> 5, lane = t & 31;       // 4 consecutive channels per lane
        float dwacc[4][4];
        #pragma unroll
        for (int cc = 0; cc < 4; cc++)
            #pragma unroll
            for (int d = 0; d < 4; d++) dwacc[cc][d] = bdw[(lane * 4 + cc) * 4 + d];
        #pragma unroll
        for (int i = 0; i < 16; i++) {
            float fx0 = 0.f, fx1 = 0.f, fx2 = 0.f, fx3 = 0.f;
            #pragma unroll
            for (int j = 0; j < 16; j++) {
                float xv = X0T[(i * 16 + j) * 8 + g];                  // broadcast
                float4 f = *(const float4*)&fc[(g * 16 + j) * CCAT + lane * 4];
                fx0 += xv * f.x; fx1 += xv * f.y; fx2 += xv * f.z; fx3 += xv * f.w;
            }
            #pragma unroll
            for (int d = 0; d < 4; d++) {
                float4 wd = *(const float4*)&ws[(d * 16 + i) * 132 + lane * 4];
                dwacc[0][d] += fx0 * wd.x;
                dwacc[1][d] += fx1 * wd.y;
                dwacc[2][d] += fx2 * wd.z;
                dwacc[3][d] += fx3 * wd.w;
            }
        }
        #pragma unroll
        for (int cc = 0; cc < 4; cc++) {
            float4 v = {dwacc[cc][0], dwacc[cc][1], dwacc[cc][2], dwacc[cc][3]};
            *(float4*)&dws[g * 512 + lane * 16 + cc * 4] = v;   // m = c*4 + d
        }
    }
    __syncthreads();

    // ---- Stage E: y = BN(elu(dw @ wpw + bpw)) ----
    {
        int o  = t & 127;
        int gs = (t >> 7) * 4;
        float acc0 = bpw[o];
        float acc1 = acc0, acc2 = acc0, acc3 = acc0;
        const float* wcol = wpw + o;
        const float* d0 = dws + (gs + 0) * 512;
        const float* d1 = dws + (gs + 1) * 512;
        const float* d2 = dws + (gs + 2) * 512;
        const float* d3 = dws + (gs + 3) * 512;
        #pragma unroll 8
        for (int m = 0; m < 512; m++) {
            float w = wcol[m * 128];
            acc0 += d0[m] * w;
            acc1 += d1[m] * w;
            acc2 += d2[m] * w;
            acc3 += d3[m] * w;
        }
        float scale = bng[o] * rsqrtf(bnv[o] + 1e-5f);
        float mu = bnm[o], be = bnb[o];
        out[(size_t)(pbase + gs + 0) * 128 + o] = (elu1(acc0) - mu) * scale + be;
        out[(size_t)(pbase + gs + 1) * 128 + o] = (elu1(acc1) - mu) * scale + be;
        out[(size_t)(pbase + gs + 2) * 128 + o] = (elu1(acc2) - mu) * scale + be;
        out[(size_t)(pbase + gs + 3) * 128 + o] = (elu1(acc3) - mu) * scale + be;
    }
}

} // namespace

extern "C" void kernel_launch(void* const* d_in, const int* in_sizes, int n_in,
                              void* d_out, int out_size) {
    const float* rep_pt = (const float*)d_in[0];
    const float* pts    = (const float*)d_in[1];
    const float* fts    = (const float*)d_in[2];
    const float* w1     = (const float*)d_in[3];
    const float* b1     = (const float*)d_in[4];
    const float* w2     = (const float*)d_in[5];
    const float* b2     = (const float*)d_in[6];
    const float* wc1    = (const float*)d_in[7];
    const float* bc1    = (const float*)d_in[8];
    const float* wx1    = (const float*)d_in[9];
    const float* bx1    = (const float*)d_in[10];
    const float* wx2    = (const float*)d_in[11];
    const float* bx2    = (const float*)d_in[12];
    const float* wdw    = (const float*)d_in[13];
    const float* bdw    = (const float*)d_in[14];
    const float* wpw    = (const float*)d_in[15];
    const float* bpw    = (const float*)d_in[16];
    const float* bng    = (const float*)d_in[17];
    const float* bnb    = (const float*)d_in[18];
    const float* bnm    = (const float*)d_in[19];
    const float* bnv    = (const float*)d_in[20];
    float* out = (float*)d_out;

    const size_t smem_bytes = (size_t)SMEM_FLOATS * sizeof(float);
    cudaFuncSetAttribute(xconv_kernel,
                         cudaFuncAttributeMaxDynamicSharedMemorySize,
                         (int)smem_bytes);

    const int n_points = 16 * 1024;           // N * P
    const int grid = n_points / G;            // 2048 CTAs
    xconv_kernel<<<grid, T, smem_bytes>>>(
        rep_pt, pts, fts, w1, b1, w2, b2, wc1, bc1,
        wx1, bx1, wx2, bx2, wdw, bdw, wpw, bpw,
        bng, bnb, bnm, bnv, out);
}

// round 2
// speedup vs baseline: 1.0645x; 1.0645x over previous
#include <cuda_runtime.h>
#include <math.h>

// XConv fused kernel for GB300 (sm_103a), round 2: 512 threads/CTA, overlap weight staging.
// Shapes: N=16,P=1024,K=16,DIMS=3,C_IN=64,C_MID=64,C_CAT=128,KK=256,DM=4,C_OUT=128

namespace {

constexpr int KNB   = 16;
constexpr int G     = 8;     // points per CTA
constexpr int T     = 512;   // threads per CTA
constexpr int CCAT  = 128;

// shared memory layout (float offsets)
constexpr int OFF_W1  = 0;        // 192
constexpr int OFF_B1  = 192;      // 64
constexpr int OFF_B2  = 256;      // 64
constexpr int OFF_PLT = 320;      // 384   plT[g][d][k]
constexpr int OFF_FC  = 704;      // 16384 fts_cat[g*16+k][128]
constexpr int OFF_WS  = 17088;    // 8448  (union: w2 4096 / wdwT 64*132=8448)
constexpr int OFF_WC1 = 25536;    // 12544 wc1 pitched 256*49
constexpr int OFF_R   = 38080;    // 8448  (union: h1 128*66 / X0T 2048+X1T 2048 / X0T+dw 4096)
constexpr int SMEM_FLOATS = 46528;  // 186112 bytes

__device__ __forceinline__ float elu1(float x) { return x > 0.f ? x : expm1f(x); }

__global__ void __launch_bounds__(T, 1)
xconv_kernel(const float* __restrict__ rep_pt, const float* __restrict__ pts,
             const float* __restrict__ fts,
             const float* __restrict__ w1,  const float* __restrict__ b1,
             const float* __restrict__ w2,  const float* __restrict__ b2,
             const float* __restrict__ wc1, const float* __restrict__ bc1,
             const float* __restrict__ wx1, const float* __restrict__ bx1,
             const float* __restrict__ wx2, const float* __restrict__ bx2,
             const float* __restrict__ wdw, const float* __restrict__ bdw,
             const float* __restrict__ wpw, const float* __restrict__ bpw,
             const float* __restrict__ bng, const float* __restrict__ bnb,
             const float* __restrict__ bnm, const float* __restrict__ bnv,
             float* __restrict__ out)
{
    extern __shared__ float sm[];
    float* w1s  = sm + OFF_W1;
    float* b1s  = sm + OFF_B1;
    float* b2s  = sm + OFF_B2;
    float* plT  = sm + OFF_PLT;   // [g][d][k] : g*48 + d*16 + k
    float* fc   = sm + OFF_FC;    // [g*16+k][128]
    float* ws   = sm + OFF_WS;    // w2, later wdwT (pitch 132)
    float* wc1s = sm + OFF_WC1;   // wc1 pitched 49
    float* R    = sm + OFF_R;

    const int t = threadIdx.x;
    const int pbase = blockIdx.x * G;

    // ---- Stage A0: stage all early weights + inputs ----
    for (int i = t; i < 192; i += T) w1s[i] = w1[i];
    if (t < 64) { b1s[t] = b1[t]; b2s[t] = b2[t]; }
    for (int i = t; i < 4096; i += T) ws[i] = w2[i];
    // wc1 (o, m=d*16+k) -> pitched 49 (conflict-free column reads)
    for (int i = t; i < 256 * 48; i += T) {
        int o = i / 48, m = i - o * 48;
        wc1s[o * 49 + m] = wc1[i];
    }
    // pts_local transposed: plT[g][d][k]
    for (int i = t; i < G * 48; i += T) {
        int g = i / 48, r = i - g * 48, d = r >> 4, k = r & 15;
        int pp = pbase + g;
        plT[i] = pts[(pp * KNB + k) * 3 + d] - rep_pt[pp * 3 + d];
    }
    // fts into fts_cat columns 64..127 (coalesced)
    for (int i = t; i < G * KNB * 64; i += T) {
        int g = i >> 10, rem = i & 1023, k = rem >> 6, c = rem & 63;
        fc[(g * KNB + k) * CCAT + 64 + c] = fts[(size_t)(pbase + g) * 1024 + rem];
    }
    __syncthreads();

    // ---- Stage A1: h1 = elu(pl @ w1 + b1)  (128 rows x 64 cols, pitch 66) ----
    float* h1 = R;
    {
        int row = t >> 2, g = row >> 4, k = row & 15, cb = (t & 3) * 16;
        float p0 = plT[g * 48 + k];
        float p1 = plT[g * 48 + 16 + k];
        float p2 = plT[g * 48 + 32 + k];
        #pragma unroll
        for (int c = 0; c < 16; c++) {
            float a = b1s[cb + c] + p0 * w1s[cb + c] + p1 * w1s[64 + cb + c]
                      + p2 * w1s[128 + cb + c];
            h1[row * 66 + cb + c] = elu1(a);
        }
    }
    __syncthreads();

    // ---- Stage A2: h2 = elu(h1 @ w2 + b2) -> fc[:, 0:64] ----
    {
        int tc = t & 15, tr = t >> 4;          // 16 col-groups x 32 row-groups
        float acc[4][4];
        #pragma unroll
        for (int i = 0; i < 4; i++)
            #pragma unroll
            for (int c = 0; c < 4; c++) acc[i][c] = b2s[tc * 4 + c];
        #pragma unroll 8
        for (int j = 0; j < 64; j++) {
            float4 w = *(const float4*)&ws[j * 64 + tc * 4];
            #pragma unroll
            for (int i = 0; i < 4; i++) {
                float hv = h1[(tr * 4 + i) * 66 + j];
                acc[i][0] += hv * w.x; acc[i][1] += hv * w.y;
                acc[i][2] += hv * w.z; acc[i][3] += hv * w.w;
            }
        }
        #pragma unroll
        for (int i = 0; i < 4; i++) {
            int row = tr * 4 + i;
            float4 o = {elu1(acc[i][0]), elu1(acc[i][1]), elu1(acc[i][2]), elu1(acc[i][3])};
            *(float4*)&fc[row * CCAT + tc * 4] = o;
        }
    }
    __syncthreads();

    // ---- wdwT staging (w2 region dead): issue now, drains under B/C ----
    for (int i = t; i < 8192; i += T) {
        int c = i >> 6, r = i & 63;            // r = d*16 + k
        ws[r * 132 + c] = wdw[i];
    }
    // (no sync: consumed after the C2 barrier)

    // ---- Stage B: X0 = elu(pl_flat @ wc1^T + bc1), transposed X0T[o][g] ----
    float* X0T = R;            // 256*8
    float* X1T = R + 2048;     // 256*8
    {
        int g = t >> 6, lane = t & 63;
        float acc[4];
        #pragma unroll
        for (int q = 0; q < 4; q++) acc[q] = bc1[lane + 64 * q];
        const float* pg = plT + g * 48;
        #pragma unroll 8
        for (int m = 0; m < 48; m++) {
            float pv = pg[m];
            #pragma unroll
            for (int q = 0; q < 4; q++) acc[q] += pv * wc1s[(lane + 64 * q) * 49 + m];
        }
        #pragma unroll
        for (int q = 0; q < 4; q++) X0T[(lane + 64 * q) * 8 + g] = elu1(acc[q]);
    }
    __syncthreads();

    // ---- Stage C1: X1 = elu(X0 @ wx1 + bx1) ----
    {
        int c = (t & 127) * 2;    // column pair
        int gq = t >> 7;          // g pair index 0..3
        float2 bb = *(const float2*)&bx1[c];
        float a00 = bb.x, a01 = bb.y, a10 = bb.x, a11 = bb.y;  // a[gi][ci]
        #pragma unroll 8
        for (int j = 0; j < 256; j++) {
            float2 w = *(const float2*)&wx1[j * 256 + c];
            float2 x = *(const float2*)&X0T[j * 8 + gq * 2];
            a00 += x.x * w.x; a01 += x.x * w.y;
            a10 += x.y * w.x; a11 += x.y * w.y;
        }
        float2 s0 = {elu1(a00), elu1(a10)};
        float2 s1 = {elu1(a01), elu1(a11)};
        *(float2*)&X1T[c * 8 + gq * 2]       = s0;
        *(float2*)&X1T[(c + 1) * 8 + gq * 2] = s1;
    }
    __syncthreads();

    // ---- Stage C2: Xf = X1 @ wx2 + bx2 (no activation) -> X0T ----
    {
        int c = (t & 127) * 2;
        int gq = t >> 7;
        float2 bb = *(const float2*)&bx2[c];
        float a00 = bb.x, a01 = bb.y, a10 = bb.x, a11 = bb.y;
        #pragma unroll 8
        for (int j = 0; j < 256; j++) {
            float2 w = *(const float2*)&wx2[j * 256 + c];
            float2 x = *(const float2*)&X1T[j * 8 + gq * 2];
            a00 += x.x * w.x; a01 += x.x * w.y;
            a10 += x.y * w.x; a11 += x.y * w.y;
        }
        float2 s0 = {a00, a10};
        float2 s1 = {a01, a11};
        *(float2*)&X0T[c * 8 + gq * 2]       = s0;
        *(float2*)&X0T[(c + 1) * 8 + gq * 2] = s1;
    }
    __syncthreads();   // also publishes wdwT

    // ---- Stage D: fts_X = X @ fts_cat, then depthwise -> dw[g][512] ----
    float* dws = R + 2048;   // X1T dead; Xf (X0T) stays live in R[0..2047]
    {
        int g = t >> 6, lane = t & 63;
        int c0 = lane * 2;
        float dwacc[2][4];
        #pragma unroll
        for (int cc = 0; cc < 2; cc++) {
            float4 bb = *(const float4*)&bdw[(c0 + cc) * 4];
            dwacc[cc][0] = bb.x; dwacc[cc][1] = bb.y;
            dwacc[cc][2] = bb.z; dwacc[cc][3] = bb.w;
        }
        #pragma unroll
        for (int i = 0; i < 16; i++) {
            float fx0 = 0.f, fx1 = 0.f;
            #pragma unroll
            for (int j = 0; j < 16; j++) {
                float xv = X0T[(i * 16 + j) * 8 + g];                 // broadcast
                float2 f = *(const float2*)&fc[(g * 16 + j) * CCAT + c0];
                fx0 += xv * f.x; fx1 += xv * f.y;
            }
            #pragma unroll
            for (int d = 0; d < 4; d++) {
                float2 wd = *(const float2*)&ws[(d * 16 + i) * 132 + c0];
                dwacc[0][d] += fx0 * wd.x;
                dwacc[1][d] += fx1 * wd.y;
            }
        }
        #pragma unroll
        for (int cc = 0; cc < 2; cc++) {
            float4 v = {dwacc[cc][0], dwacc[cc][1], dwacc[cc][2], dwacc[cc][3]};
            *(float4*)&dws[g * 512 + (c0 + cc) * 4] = v;   // m = c*4 + d
        }
    }
    __syncthreads();

    // ---- Stage E: y = BN(elu(dw @ wpw + bpw)) ----
    {
        int o = (t & 63) * 2;
        int g = t >> 6;
        float2 bb = *(const float2*)&bpw[o];
        float a0 = bb.x, a1 = bb.y;
        const float* dg = dws + g * 512;
        #pragma unroll 8
        for (int m = 0; m < 512; m++) {
            float2 w = *(const float2*)&wpw[m * 128 + o];
            float dv = dg[m];                                   // broadcast
            a0 += dv * w.x; a1 += dv * w.y;
        }
        float2 gv = *(const float2*)&bng[o];
        float2 vv = *(const float2*)&bnv[o];
        float2 mv = *(const float2*)&bnm[o];
        float2 ev = *(const float2*)&bnb[o];
        float s0 = gv.x * rsqrtf(vv.x + 1e-5f);
        float s1 = gv.y * rsqrtf(vv.y + 1e-5f);
        float2 y = {(elu1(a0) - mv.x) * s0 + ev.x,
                    (elu1(a1) - mv.y) * s1 + ev.y};
        *(float2*)&out[(size_t)(pbase + g) * 128 + o] = y;
    }
}

} // namespace

extern "C" void kernel_launch(void* const* d_in, const int* in_sizes, int n_in,
                              void* d_out, int out_size) {
    const float* rep_pt = (const float*)d_in[0];
    const float* pts    = (const float*)d_in[1];
    const float* fts    = (const float*)d_in[2];
    const float* w1     = (const float*)d_in[3];
    const float* b1     = (const float*)d_in[4];
    const float* w2     = (const float*)d_in[5];
    const float* b2     = (const float*)d_in[6];
    const float* wc1    = (const float*)d_in[7];
    const float* bc1    = (const float*)d_in[8];
    const float* wx1    = (const float*)d_in[9];
    const float* bx1    = (const float*)d_in[10];
    const float* wx2    = (const float*)d_in[11];
    const float* bx2    = (const float*)d_in[12];
    const float* wdw    = (const float*)d_in[13];
    const float* bdw    = (const float*)d_in[14];
    const float* wpw    = (const float*)d_in[15];
    const float* bpw    = (const float*)d_in[16];
    const float* bng    = (const float*)d_in[17];
    const float* bnb    = (const float*)d_in[18];
    const float* bnm    = (const float*)d_in[19];
    const float* bnv    = (const float*)d_in[20];
    float* out = (float*)d_out;

    const size_t smem_bytes = (size_t)SMEM_FLOATS * sizeof(float);
    cudaFuncSetAttribute(xconv_kernel,
                         cudaFuncAttributeMaxDynamicSharedMemorySize,
                         (int)smem_bytes);

    const int n_points = 16 * 1024;
    const int grid = n_points / G;   // 2048 CTAs
    xconv_kernel<<<grid, T, smem_bytes>>>(
        rep_pt, pts, fts, w1, b1, w2, b2, wc1, bc1,
        wx1, bx1, wx2, bx2, wdw, bdw, wpw, bpw,
        bng, bnb, bnm, bnv, out);
}